// round 12
// baseline (speedup 1.0000x reference)
#include <cuda_runtime.h>
#include <cuda_bf16.h>
#include <math_constants.h>
#include <cstdint>

#define BATCH 2
#define NP    4096
#define NPH   2048           // half of NP (knn split)
#define NQ    16384
#define FDIM  448            // 64 + 128 + 256
#define AGK   480            // gemm1 K: 448 interp + 3 query + 29 pad
#define NPTS  (BATCH * NQ)   // 32768 query points
#define MPTS  (BATCH * NP)   // 8192 original points
#define NFCTA (MPTS / 128)   // 64 feature CTAs

// ---------------- scratch (device globals; no allocation allowed) -----------
__device__ float g_fall[MPTS * FDIM];          // point-major fp32 (f1|f2|f3)
__device__ int   g_pmax[NFCTA * 256];          // per-feature-CTA col max (f3)
__device__ float g_b1[BATCH * 256];            // gemm1 bias incl. global feats
__device__ int   g_knni[NPTS * 3];
__device__ float g_knnw[NPTS * 3];
__device__ float g_kcd[NPTS * 6];              // knn candidates (2 halves x 3)
__device__ int   g_kci[NPTS * 6];
__device__ __nv_bfloat16 g_r1h[256 * AGK],  g_r1l[256 * AGK];   // remapped cols
__device__ __nv_bfloat16 g_r2h[128 * 256],  g_r2l[128 * 256];
__device__ __nv_bfloat16 g_r3h[64 * 128],   g_r3l[64 * 128];

// ---------------- helpers -----------------------------------------------------
__device__ __forceinline__ uint32_t smem_u32(const void* p) {
    uint32_t a;
    asm("{ .reg .u64 t; cvta.to.shared.u64 t, %1; cvt.u32.u64 %0, t; }" : "=r"(a) : "l"(p));
    return a;
}
__device__ __forceinline__ void cp16(uint32_t dst, const void* src) {
    asm volatile("cp.async.cg.shared.global [%0], [%1], 16;" :: "r"(dst), "l"(src));
}
#define CP_COMMIT() asm volatile("cp.async.commit_group;" ::: "memory")

__device__ __forceinline__ void ldm_x4(uint32_t* r, uint32_t addr) {
    asm volatile("ldmatrix.sync.aligned.m8n8.x4.shared.b16 {%0,%1,%2,%3}, [%4];"
                 : "=r"(r[0]), "=r"(r[1]), "=r"(r[2]), "=r"(r[3]) : "r"(addr));
}
__device__ __forceinline__ void mma16816(float* c, const uint32_t* a, const uint32_t* b) {
    asm volatile(
        "mma.sync.aligned.m16n8k16.row.col.f32.bf16.bf16.f32 "
        "{%0,%1,%2,%3}, {%4,%5,%6,%7}, {%8,%9}, {%0,%1,%2,%3};"
        : "+f"(c[0]), "+f"(c[1]), "+f"(c[2]), "+f"(c[3])
        : "r"(a[0]), "r"(a[1]), "r"(a[2]), "r"(a[3]), "r"(b[0]), "r"(b[1]));
}
__device__ __forceinline__ void split_bf16(float v, __nv_bfloat16& h, __nv_bfloat16& l) {
    h = __float2bfloat16(v);
    l = __float2bfloat16(v - __bfloat162float(h));
}
__device__ __forceinline__ uint32_t pck(__nv_bfloat16 a, __nv_bfloat16 b) {
    return (uint32_t)*(unsigned short*)&a | ((uint32_t)*(unsigned short*)&b << 16);
}

#define PKB 80                       // smem row pitch bytes (32 bf16 + 16B pad)
#define APL (128 * PKB)              // A plane bytes (10240)
#define H1CHK (2 * APL)              // one staged chunk: hi+lo planes (20480)

// ---------------- gemm1 bias: rb1 + global-feature fold (reduces g_pmax) -----
__global__ void __launch_bounds__(256) gbias_kernel(const float* __restrict__ r1,
                                                    const float* __restrict__ rb1) {
    __shared__ float sgm[256];
    int b = blockIdx.x, n = threadIdx.x;
    int m = 0;
#pragma unroll 8
    for (int c = 0; c < NFCTA / BATCH; c++)
        m = max(m, g_pmax[(b * (NFCTA / BATCH) + c) * 256 + n]);
    sgm[n] = __int_as_float(m);
    __syncthreads();
    const float* wr = r1 + n * 707 + 451;
    float acc = rb1[n];
#pragma unroll 8
    for (int j = 0; j < 256; j++)
        acc = fmaf(wr[j], sgm[j], acc);
    g_b1[b * 256 + n] = acc;
}

// ---------------- fused weight split: r1 (remapped) | r2 | r3 ----------------
__global__ void __launch_bounds__(256) split_all_kernel(
    const float* __restrict__ r1, const float* __restrict__ r2,
    const float* __restrict__ r3) {
    int i = blockIdx.x * 256 + threadIdx.x;
    if (i >= 163840) return;
    float v = 0.0f;
    __nv_bfloat16 *hi, *lo; int off;
    if (i < 122880) {
        off = i; hi = g_r1h; lo = g_r1l;
        int r = off / AGK, k = off - r * AGK;
        if (k < 448)      v = r1[r * 707 + 3 + k];     // interp channels
        else if (k < 451) v = r1[r * 707 + (k - 448)]; // query coords
    } else if (i < 155648) {
        off = i - 122880; hi = g_r2h; lo = g_r2l;
        v = r2[off];
    } else {
        off = i - 155648; hi = g_r3h; lo = g_r3l;
        v = r3[off];
    }
    __nv_bfloat16 h, l; split_bf16(v, h, l);
    hi[off] = h; lo[off] = l;
}

// ---------------- KNN part 1: top-3 within one half of the points ------------
__global__ void __launch_bounds__(256) knn_part_kernel(const float* __restrict__ op,
                                                       const float* __restrict__ qp) {
    __shared__ float4 sp[NPH];            // 32 KB
    int b = blockIdx.y, half = blockIdx.z;
    int tid = threadIdx.x;
    int jbase = half * NPH;
    for (int i = tid; i < NPH; i += 256) {
        float x = op[b * 3 * NP + 0 * NP + jbase + i];
        float y = op[b * 3 * NP + 1 * NP + jbase + i];
        float z = op[b * 3 * NP + 2 * NP + jbase + i];
        sp[i] = make_float4(x, y, z, fmaf(x, x, fmaf(y, y, z * z)));
    }
    __syncthreads();

    int q = blockIdx.x * 256 + tid;
    float qx = qp[b * 3 * NQ + 0 * NQ + q];
    float qy = qp[b * 3 * NQ + 1 * NQ + q];
    float qz = qp[b * 3 * NQ + 2 * NQ + q];
    float nx = -2.0f * qx, ny = -2.0f * qy, nz = -2.0f * qz;

    float d0 = CUDART_INF_F, d1 = CUDART_INF_F, d2 = CUDART_INF_F;
    int i0 = 0, i1 = 0, i2 = 0;
#pragma unroll 8
    for (int j = 0; j < NPH; j++) {
        float4 o = sp[j];
        float d = fmaf(o.x, nx, fmaf(o.y, ny, fmaf(o.z, nz, o.w)));
        if (d < d2) {
            if (d < d1) {
                d2 = d1; i2 = i1;
                if (d < d0) { d1 = d0; i1 = i0; d0 = d; i0 = j; }
                else        { d1 = d;  i1 = j; }
            } else { d2 = d; i2 = j; }
        }
    }
    int base = ((b * NQ + q) * 2 + half) * 3;
    g_kcd[base + 0] = d0; g_kci[base + 0] = jbase + i0;
    g_kcd[base + 1] = d1; g_kci[base + 1] = jbase + i1;
    g_kcd[base + 2] = d2; g_kci[base + 2] = jbase + i2;
}

// ---------------- KNN part 2: merge halves, compute weights ------------------
__global__ void __launch_bounds__(256) knn_merge_kernel(const float* __restrict__ op,
                                                        const float* __restrict__ qp) {
    int i = blockIdx.x * 256 + threadIdx.x;   // 0..NPTS-1
    int b = i >> 14, q = i & (NQ - 1);
    float d0 = CUDART_INF_F, d1 = CUDART_INF_F, d2 = CUDART_INF_F;
    int i0 = 0, i1 = 0, i2 = 0;
#pragma unroll
    for (int c = 0; c < 6; c++) {
        float d = g_kcd[i * 6 + c];
        int   j = g_kci[i * 6 + c];
        if (d < d2) {
            if (d < d1) {
                d2 = d1; i2 = i1;
                if (d < d0) { d1 = d0; i1 = i0; d0 = d; i0 = j; }
                else        { d1 = d;  i1 = j; }
            } else { d2 = d; i2 = j; }
        }
    }
    float qx = qp[b * 3 * NQ + 0 * NQ + q];
    float qy = qp[b * 3 * NQ + 1 * NQ + q];
    float qz = qp[b * 3 * NQ + 2 * NQ + q];
    int   ii[3] = {i0, i1, i2};
    float rc[3];
    float s = 0.0f;
#pragma unroll
    for (int k = 0; k < 3; k++) {
        float dx = op[b * 3 * NP + 0 * NP + ii[k]] - qx;
        float dy = op[b * 3 * NP + 1 * NP + ii[k]] - qy;
        float dz = op[b * 3 * NP + 2 * NP + ii[k]] - qz;
        float dist = sqrtf(fmaf(dx, dx, fmaf(dy, dy, dz * dz)));
        rc[k] = 1.0f / (dist + 1e-8f);
        s += rc[k];
    }
    float inv = 1.0f / s;
#pragma unroll
    for (int k = 0; k < 3; k++) {
        g_knni[i * 3 + k] = ii[k];
        g_knnw[i * 3 + k] = rc[k] * inv;
    }
}

// ---------------- FEATURE MEGA: mlp1 -> mlp2 -> mlp3 -> pmax, one kernel -----
// Weights split inline from fp32 (no dependency on split_all).
//   [0,      40960)  f1 chunks (2 x 20480)
//   [40960, 122880)  f2 chunks (4 x 20480)
//   [122880,163840)  W buffer (W2: 2x10240 | W3: 2x20480)
//   [163840,164864)  w1 (192) + b1 (64) floats
#define FH1  0
#define FH2  40960
#define FWO  122880
#define FCO  163840
#define SMFEAT 164864

__global__ void __launch_bounds__(512) feature_mega(
    const float* __restrict__ op,
    const float* __restrict__ w1, const float* __restrict__ b1,
    const float* __restrict__ w2, const float* __restrict__ b2,
    const float* __restrict__ w3, const float* __restrict__ b3) {
    extern __shared__ char smem[];
    const int t = threadIdx.x;
    const int lane = t & 31, warp = t >> 5;
    const int wm = warp >> 2, wn = warp & 3;
    const int m0 = blockIdx.x * 128;
    const int b  = m0 >> 12;
    const int pt0 = m0 & (NP - 1);

    if (t < 256) g_pmax[blockIdx.x * 256 + t] = 0;   // own row; reduced at end

    float* sw1 = (float*)(smem + FCO);
    float* sb1 = sw1 + 192;
    if (t < 192) sw1[t] = w1[t];
    else if (t >= 256 && t < 320) sb1[t - 256] = b1[t - 256];
    __syncthreads();

    // ---- phase A: f1 = relu(w1*xyz + b1), fp32 to fall + smem chunks --------
#pragma unroll
    for (int u = 0; u < 2; u++) {
        int e = t + u * 512;
        int row = e >> 3, c8 = e & 7;
        int pt = pt0 + row;
        float x = op[b * 3 * NP + pt];
        float y = op[b * 3 * NP + NP + pt];
        float z = op[b * 3 * NP + 2 * NP + pt];
        float v[8];
        __nv_bfloat16 h[8], l[8];
#pragma unroll
        for (int j = 0; j < 8; j++) {
            int c = c8 * 8 + j;
            v[j] = fmaxf(fmaf(sw1[c*3], x, fmaf(sw1[c*3+1], y,
                        fmaf(sw1[c*3+2], z, sb1[c]))), 0.0f);
            split_bf16(v[j], h[j], l[j]);
        }
        float* fd = g_fall + (size_t)(m0 + row) * FDIM + c8 * 8;
        *(float4*)fd       = make_float4(v[0], v[1], v[2], v[3]);
        *(float4*)(fd + 4) = make_float4(v[4], v[5], v[6], v[7]);
        char* ckb = smem + FH1 + (c8 >> 2) * H1CHK;
        int off = row * PKB + (c8 & 3) * 16;
        *(uint4*)(ckb + off) =
            make_uint4(pck(h[0],h[1]), pck(h[2],h[3]), pck(h[4],h[5]), pck(h[6],h[7]));
        *(uint4*)(ckb + APL + off) =
            make_uint4(pck(l[0],l[1]), pck(l[2],l[3]), pck(l[4],l[5]), pck(l[6],l[7]));
    }
    __syncthreads();

    // ---- phase B: gemm 64 -> 128 (W2 split inline from fp32) ----------------
    constexpr int W2PL = 128 * PKB;   // 10240
    float acc2[2][4][4];
#pragma unroll
    for (int i = 0; i < 2; i++)
#pragma unroll
        for (int j = 0; j < 4; j++)
#pragma unroll
            for (int v = 0; v < 4; v++) acc2[i][j][v] = 0.0f;

    for (int c = 0; c < 2; c++) {
        {   // 128 rows x 4 octets = 512 (one per thread)
            int row = t >> 2, oct = t & 3;
            const float* src = w2 + row * 64 + c * 32 + oct * 8;
            float4 a = *(const float4*)src, q = *(const float4*)(src + 4);
            float v[8] = {a.x, a.y, a.z, a.w, q.x, q.y, q.z, q.w};
            __nv_bfloat16 h[8], l[8];
#pragma unroll
            for (int j = 0; j < 8; j++) split_bf16(v[j], h[j], l[j]);
            char* dst = smem + FWO;
            int off = row * PKB + oct * 16;
            *(uint4*)(dst + off) =
                make_uint4(pck(h[0],h[1]), pck(h[2],h[3]), pck(h[4],h[5]), pck(h[6],h[7]));
            *(uint4*)(dst + W2PL + off) =
                make_uint4(pck(l[0],l[1]), pck(l[2],l[3]), pck(l[4],l[5]), pck(l[6],l[7]));
        }
        __syncthreads();

        char* abase = smem + FH1 + c * H1CHK;
#pragma unroll
        for (int kk = 0; kk < 2; kk++) {
            uint32_t afr[2][2][4];
#pragma unroll
            for (int pl = 0; pl < 2; pl++)
#pragma unroll
                for (int mt = 0; mt < 2; mt++) {
                    uint32_t a = smem_u32(abase + pl * APL
                        + (wm * 32 + mt * 16 + (lane & 15)) * PKB
                        + (kk * 16 + (lane >> 4) * 8) * 2);
                    ldm_x4(afr[pl][mt], a);
                }
#pragma unroll
            for (int nt = 0; nt < 4; nt++) {
                const char* bp = smem + FWO
                    + (wn * 32 + nt * 8 + (lane >> 2)) * PKB
                    + (kk * 16 + (lane & 3) * 2) * 2;
                uint32_t bh[2], bl[2];
                bh[0] = *(const uint32_t*)bp;
                bh[1] = *(const uint32_t*)(bp + 16);
                bl[0] = *(const uint32_t*)(bp + W2PL);
                bl[1] = *(const uint32_t*)(bp + W2PL + 16);
#pragma unroll
                for (int mt = 0; mt < 2; mt++) {
                    mma16816(acc2[mt][nt], afr[0][mt], bh);
                    mma16816(acc2[mt][nt], afr[0][mt], bl);
                    mma16816(acc2[mt][nt], afr[1][mt], bh);
                }
            }
        }
        __syncthreads();
    }

    // f2 = relu(acc2 + b2): fp32 to fall col 64.. + smem chunks
#pragma unroll
    for (int mt = 0; mt < 2; mt++)
#pragma unroll
        for (int nt = 0; nt < 4; nt++) {
            int rowl = wm * 32 + mt * 16 + (lane >> 2);
            int col = wn * 32 + nt * 8 + (lane & 3) * 2;
            float b0 = b2[col], b1v = b2[col + 1];
            float v0 = fmaxf(acc2[mt][nt][0] + b0, 0.0f);
            float v1 = fmaxf(acc2[mt][nt][1] + b1v, 0.0f);
            float v2 = fmaxf(acc2[mt][nt][2] + b0, 0.0f);
            float v3 = fmaxf(acc2[mt][nt][3] + b1v, 0.0f);
            *(float2*)(g_fall + (size_t)(m0 + rowl) * FDIM + 64 + col) = make_float2(v0, v1);
            *(float2*)(g_fall + (size_t)(m0 + rowl + 8) * FDIM + 64 + col) = make_float2(v2, v3);
            char* ckb = smem + FH2 + (col >> 5) * H1CHK;
            int ci = (col & 31) * 2;
            __nv_bfloat16 h0, l0, h1, l1;
            split_bf16(v0, h0, l0); split_bf16(v1, h1, l1);
            *(uint32_t*)(ckb + rowl * PKB + ci)       = pck(h0, h1);
            *(uint32_t*)(ckb + APL + rowl * PKB + ci) = pck(l0, l1);
            split_bf16(v2, h0, l0); split_bf16(v3, h1, l1);
            *(uint32_t*)(ckb + (rowl + 8) * PKB + ci)       = pck(h0, h1);
            *(uint32_t*)(ckb + APL + (rowl + 8) * PKB + ci) = pck(l0, l1);
        }
    __syncthreads();

    // ---- phase C: gemm 128 -> 256 (W3 split inline from fp32) ---------------
    constexpr int W3PL = 256 * PKB;   // 20480
    float acc3[2][8][4];
#pragma unroll
    for (int i = 0; i < 2; i++)
#pragma unroll
        for (int j = 0; j < 8; j++)
#pragma unroll
            for (int v = 0; v < 4; v++) acc3[i][j][v] = 0.0f;

    for (int c = 0; c < 4; c++) {
#pragma unroll
        for (int u = 0; u < 2; u++) {    // 256 rows x 4 octets = 1024
            int e = t + u * 512;
            int row = e >> 2, oct = e & 3;
            const float* src = w3 + row * 128 + c * 32 + oct * 8;
            float4 a = *(const float4*)src, q = *(const float4*)(src + 4);
            float v[8] = {a.x, a.y, a.z, a.w, q.x, q.y, q.z, q.w};
            __nv_bfloat16 h[8], l[8];
#pragma unroll
            for (int j = 0; j < 8; j++) split_bf16(v[j], h[j], l[j]);
            char* dst = smem + FWO;
            int off = row * PKB + oct * 16;
            *(uint4*)(dst + off) =
                make_uint4(pck(h[0],h[1]), pck(h[2],h[3]), pck(h[4],h[5]), pck(h[6],h[7]));
            *(uint4*)(dst + W3PL + off) =
                make_uint4(pck(l[0],l[1]), pck(l[2],l[3]), pck(l[4],l[5]), pck(l[6],l[7]));
        }
        __syncthreads();

        char* abase = smem + FH2 + c * H1CHK;
#pragma unroll
        for (int kk = 0; kk < 2; kk++) {
            uint32_t afr[2][2][4];
#pragma unroll
            for (int pl = 0; pl < 2; pl++)
#pragma unroll
                for (int mt = 0; mt < 2; mt++) {
                    uint32_t a = smem_u32(abase + pl * APL
                        + (wm * 32 + mt * 16 + (lane & 15)) * PKB
                        + (kk * 16 + (lane >> 4) * 8) * 2);
                    ldm_x4(afr[pl][mt], a);
                }
#pragma unroll
            for (int nt = 0; nt < 8; nt++) {
                const char* bp = smem + FWO
                    + (wn * 64 + nt * 8 + (lane >> 2)) * PKB
                    + (kk * 16 + (lane & 3) * 2) * 2;
                uint32_t bh[2], bl[2];
                bh[0] = *(const uint32_t*)bp;
                bh[1] = *(const uint32_t*)(bp + 16);
                bl[0] = *(const uint32_t*)(bp + W3PL);
                bl[1] = *(const uint32_t*)(bp + W3PL + 16);
#pragma unroll
                for (int mt = 0; mt < 2; mt++) {
                    mma16816(acc3[mt][nt], afr[0][mt], bh);
                    mma16816(acc3[mt][nt], afr[0][mt], bl);
                    mma16816(acc3[mt][nt], afr[1][mt], bh);
                }
            }
        }
        __syncthreads();
    }

    // f3 = relu(acc3 + b3): fp32 to fall col 192.. + per-CTA pmax
#pragma unroll
    for (int mt = 0; mt < 2; mt++)
#pragma unroll
        for (int nt = 0; nt < 8; nt++) {
            int rowl = wm * 32 + mt * 16 + (lane >> 2);
            int col = wn * 64 + nt * 8 + (lane & 3) * 2;
            float b0 = b3[col], b1v = b3[col + 1];
            float v0 = fmaxf(acc3[mt][nt][0] + b0, 0.0f);
            float v1 = fmaxf(acc3[mt][nt][1] + b1v, 0.0f);
            float v2 = fmaxf(acc3[mt][nt][2] + b0, 0.0f);
            float v3 = fmaxf(acc3[mt][nt][3] + b1v, 0.0f);
            *(float2*)(g_fall + (size_t)(m0 + rowl) * FDIM + 192 + col) = make_float2(v0, v1);
            *(float2*)(g_fall + (size_t)(m0 + rowl + 8) * FDIM + 192 + col) = make_float2(v2, v3);
        }
#pragma unroll
    for (int nt = 0; nt < 8; nt++) {
        int col = wn * 64 + nt * 8 + (lane & 3) * 2;
        float b0 = b3[col], b1v = b3[col + 1];
        float mA = fmaxf(fmaxf(acc3[0][nt][0], acc3[0][nt][2]),
                         fmaxf(acc3[1][nt][0], acc3[1][nt][2])) + b0;
        float mB = fmaxf(fmaxf(acc3[0][nt][1], acc3[0][nt][3]),
                         fmaxf(acc3[1][nt][1], acc3[1][nt][3])) + b1v;
        mA = fmaxf(mA, 0.0f); mB = fmaxf(mB, 0.0f);
#pragma unroll
        for (int o = 4; o < 32; o <<= 1) {
            mA = fmaxf(mA, __shfl_xor_sync(0xffffffffu, mA, o));
            mB = fmaxf(mB, __shfl_xor_sync(0xffffffffu, mB, o));
        }
        if ((lane >> 2) == 0) {   // 4 warps (wm) race within own CTA row: atomicMax
            atomicMax(&g_pmax[blockIdx.x * 256 + col],     __float_as_int(mA));
            atomicMax(&g_pmax[blockIdx.x * 256 + col + 1], __float_as_int(mB));
        }
    }
}

// ---------------- MEGA: gemm1(interp,480->256) -> 256->128 -> 128->64 -> 1 ---
#define SS1    (2 * APL + 2 * 256 * PKB)   // 61440
#define W3CHK  (2 * 64 * PKB)              // 10240
#define G1OFF  40960
#define KOFF   163840
#define H1OFF  40960
#define W2OFF  204800
#define W2PLM  (128 * PKB)                 // 10240
#define H2OFF  40960
#define SPOFF  163840
#define SMEGA  225280

__global__ void __launch_bounds__(512) tgemm_mega(
    const float* __restrict__ fall, const float* __restrict__ qp,
    const __nv_bfloat16* __restrict__ W1hi, const __nv_bfloat16* __restrict__ W1lo,
    const __nv_bfloat16* __restrict__ W2hi, const __nv_bfloat16* __restrict__ W2lo,
    const __nv_bfloat16* __restrict__ W3hi, const __nv_bfloat16* __restrict__ W3lo,
    const float* __restrict__ rb2, const float* __restrict__ rb3,
    const float* __restrict__ r4, const float* __restrict__ rb4,
    float* __restrict__ out) {
    extern __shared__ char smem[];
    const int t = threadIdx.x;
    const int lane = t & 31, warp = t >> 5;
    const int wm = warp >> 2, wn = warp & 3;
    const int m0 = blockIdx.x * 128;
    const int b  = m0 >> 14;

    int*   si  = (int*)(smem + KOFF);
    float* swt = (float*)(smem + KOFF + 1536);
    if (t < 128) {
#pragma unroll
        for (int j = 0; j < 3; j++) {
            si[t * 3 + j]  = g_knni[(m0 + t) * 3 + j];
            swt[t * 3 + j] = g_knnw[(m0 + t) * 3 + j];
        }
    }

    // r3 preload into [0, 40960): joins the first cp.async group
    {
        char* w3b = smem;
#pragma unroll
        for (int u = 0; u < 4; u++) {
            int e = t + u * 512;
            int pl = e >> 10, rem = e & 1023;
            int ck = rem >> 8, r2m = rem & 255;
            int row = r2m >> 2, seg = r2m & 3;
            const char* src = (const char*)(pl ? W3lo : W3hi)
                + ((size_t)row * 128 + ck * 32) * 2 + seg * 16;
            cp16(smem_u32(w3b + ck * W3CHK + pl * (64 * PKB) + row * PKB + seg * 16), src);
        }
    }

    // ================= PHASE 1: gemm1 480 -> 256 (pipelined A-gather) ========
    constexpr int NC1 = AGK / 32;   // 15
    float acc[2][8][4];
#pragma unroll
    for (int i = 0; i < 2; i++)
#pragma unroll
        for (int j = 0; j < 8; j++)
#pragma unroll
            for (int v = 0; v < 4; v++) acc[i][j][v] = 0.0f;

    float4 gA[2][3];   // register-pipelined gathers (2 elems x 3 neighbors)

    auto stageW1 = [&](int buf, int c) {
        char* base = smem + G1OFF + buf * SS1;
#pragma unroll
        for (int u = 0; u < 4; u++) {
            int e = t + u * 512;
            int pl = e >> 10, rem = e & 1023;
            int row = rem >> 2, seg = rem & 3;
            const char* src = (const char*)(pl ? W1lo : W1hi)
                + ((size_t)row * AGK + c * 32) * 2 + seg * 16;
            cp16(smem_u32(base + 2 * APL + pl * (256 * PKB) + row * PKB + seg * 16), src);
        }
        CP_COMMIT();
    };

    auto gatherA = [&](int c) {
#pragma unroll
        for (int u = 0; u < 2; u++) {
            int e = t + u * 512;
            int row = e >> 3, c4 = e & 7;
            int ch = c * 32 + c4 * 4;
            if (ch < 448) {
                const float* fr = fall + (size_t)(b * NP) * FDIM + ch;
                gA[u][0] = *(const float4*)(fr + (size_t)si[row * 3 + 0] * FDIM);
                gA[u][1] = *(const float4*)(fr + (size_t)si[row * 3 + 1] * FDIM);
                gA[u][2] = *(const float4*)(fr + (size_t)si[row * 3 + 2] * FDIM);
            }
        }
    };

    auto storeA = [&](char* base, int c) {
#pragma unroll
        for (int u = 0; u < 2; u++) {
            int e = t + u * 512;
            int row = e >> 3, c4 = e & 7;
            int ch = c * 32 + c4 * 4;
            float v0, v1, v2, v3;
            if (ch < 448) {
                float wa = swt[row * 3 + 0], wb = swt[row * 3 + 1], wc = swt[row * 3 + 2];
                v0 = wa * gA[u][0].x + wb * gA[u][1].x + wc * gA[u][2].x;
                v1 = wa * gA[u][0].y + wb * gA[u][1].y + wc * gA[u][2].y;
                v2 = wa * gA[u][0].z + wb * gA[u][1].z + wc * gA[u][2].z;
                v3 = wa * gA[u][0].w + wb * gA[u][1].w + wc * gA[u][2].w;
            } else if (ch == 448) {
                int qi = (m0 + row) & (NQ - 1);
                v0 = qp[b * 3 * NQ + 0 * NQ + qi];
                v1 = qp[b * 3 * NQ + 1 * NQ + qi];
                v2 = qp[b * 3 * NQ + 2 * NQ + qi];
                v3 = 0.0f;
            } else {
                v0 = v1 = v2 = v3 = 0.0f;
            }
            __nv_bfloat16 h0, l0, h1, l1, h2, l2, h3, l3;
            split_bf16(v0, h0, l0); split_bf16(v1, h1, l1);
            split_bf16(v2, h2, l2); split_bf16(v3, h3, l3);
            int off = row * PKB + (c4 >> 1) * 16 + (c4 & 1) * 8;
            *(uint2*)(base + off)       = make_uint2(pck(h0, h1), pck(h2, h3));
            *(uint2*)(base + APL + off) = make_uint2(pck(l0, l1), pck(l2, l3));
        }
    };

    __syncthreads();   // si/swt visible before gathers
    gatherA(0);
    stageW1(0, 0);
    for (int c = 0; c < NC1; c++) {
        char* base = smem + G1OFF + (c & 1) * SS1;
        storeA(base, c);
        if (c + 1 < NC1) {
            stageW1((c + 1) & 1, c + 1);
            gatherA(c + 1);    // overlap gather latency with chunk-c compute
            asm volatile("cp.async.wait_group 1;" ::: "memory");
        } else {
            asm volatile("cp.async.wait_group 0;" ::: "memory");
        }
        __syncthreads();
#pragma unroll
        for (int kk = 0; kk < 2; kk++) {
            uint32_t afr[2][2][4];
#pragma unroll
            for (int pl = 0; pl < 2; pl++)
#pragma unroll
                for (int mt = 0; mt < 2; mt++) {
                    uint32_t a = smem_u32(base + pl * APL
                        + (wm * 32 + mt * 16 + (lane & 15)) * PKB
                        + (kk * 16 + (lane >> 4) * 8) * 2);
                    ldm_x4(afr[pl][mt], a);
                }
#pragma unroll
            for (int nt = 0; nt < 8; nt++) {
                const char* bp = base + 2 * APL
                    + (wn * 64 + nt * 8 + (lane >> 2)) * PKB
                    + (kk * 16 + (lane & 3) * 2) * 2;
                uint32_t bh[2], bl[2];
                bh[0] = *(const uint32_t*)bp;
                bh[1] = *(const uint32_t*)(bp + 16);
                bl[0] = *(const uint32_t*)(bp + 256 * PKB);
                bl[1] = *(const uint32_t*)(bp + 256 * PKB + 16);
#pragma unroll
                for (int mt = 0; mt < 2; mt++) {
                    mma16816(acc[mt][nt], afr[0][mt], bh);
                    mma16816(acc[mt][nt], afr[0][mt], bl);
                    mma16816(acc[mt][nt], afr[1][mt], bh);
                }
            }
        }
        __syncthreads();
    }

    // h1 = relu(acc + g_b1) -> smem chunk layout
    {
        const float* bias = g_b1 + b * 256;
#pragma unroll
        for (int mt = 0; mt < 2; mt++)
#pragma unroll
            for (int nt = 0; nt < 8; nt++) {
                int rowl = wm * 32 + mt * 16 + (lane >> 2);
                int col = wn * 64 + nt * 8 + (lane & 3) * 2;
                float b0 = bias[col], b1 = bias[col + 1];
                float v0 = fmaxf(acc[mt][nt][0] + b0, 0.0f);
                float v1 = fmaxf(acc[mt][nt][1] + b1, 0.0f);
                float v2 = fmaxf(acc[mt][nt][2] + b0, 0.0f);
                float v3 = fmaxf(acc[mt][nt][3] + b1, 0.0f);
                char* ckb = smem + H1OFF + (col >> 5) * H1CHK;
                int ci = (col & 31) * 2;
                __nv_bfloat16 h0, l0, h1, l1;
                split_bf16(v0, h0, l0); split_bf16(v1, h1, l1);
                *(uint32_t*)(ckb + rowl * PKB + ci)       = pck(h0, h1);
                *(uint32_t*)(ckb + APL + rowl * PKB + ci) = pck(l0, l1);
                split_bf16(v2, h0, l0); split_bf16(v3, h1, l1);
                *(uint32_t*)(ckb + (rowl + 8) * PKB + ci)       = pck(h0, h1);
                *(uint32_t*)(ckb + APL + (rowl + 8) * PKB + ci) = pck(l0, l1);
            }
    }
    __syncthreads();

    // ================= PHASE 2: gemm2 256 -> 128 (W2 single buffer) ==========
    float acc2[2][4][4];
#pragma unroll
    for (int i = 0; i < 2; i++)
#pragma unroll
        for (int j = 0; j < 4; j++)
#pragma unroll
            for (int v = 0; v < 4; v++) acc2[i][j][v] = 0.0f;

    for (int c = 0; c < 8; c++) {
#pragma unroll
        for (int u = 0; u < 2; u++) {
            int e = t + u * 512;
            int pl = e >> 9, rem = e & 511;
            int row = rem >> 2, seg = rem & 3;
            const char* src = (const char*)(pl ? W2lo : W2hi)
                + ((size_t)row * 256 + c * 32) * 2 + seg * 16;
            cp16(smem_u32(smem + W2OFF + pl * W2PLM + row * PKB + seg * 16), src);
        }
        CP_COMMIT();
        asm volatile("cp.async.wait_group 0;" ::: "memory");
        __syncthreads();

        char* abase = smem + H1OFF + c * H1CHK;
#pragma unroll
        for (int kk = 0; kk < 2; kk++) {
            uint32_t afr[2][2][4];
#pragma unroll
            for (int pl = 0; pl < 2; pl++)
#pragma unroll
                for (int mt = 0; mt < 2; mt++) {
                    uint32_t a = smem_u32(abase + pl * APL
                        + (wm * 32 + mt * 16 + (lane & 15)) * PKB
                        + (kk * 16 + (lane >> 4) * 8) * 2);
                    ldm_x4(afr[pl][mt], a);
                }
#pragma unroll
            for (int nt = 0; nt < 4; nt++) {
                const char* bp = smem + W2OFF
                    + (wn * 32 + nt * 8 + (lane >> 2)) * PKB
                    + (kk * 16 + (lane & 3) * 2) * 2;
                uint32_t bh[2], bl[2];
                bh[0] = *(const uint32_t*)bp;
                bh[1] = *(const uint32_t*)(bp + 16);
                bl[0] = *(const uint32_t*)(bp + W2PLM);
                bl[1] = *(const uint32_t*)(bp + W2PLM + 16);
#pragma unroll
                for (int mt = 0; mt < 2; mt++) {
                    mma16816(acc2[mt][nt], afr[0][mt], bh);
                    mma16816(acc2[mt][nt], afr[0][mt], bl);
                    mma16816(acc2[mt][nt], afr[1][mt], bh);
                }
            }
        }
        __syncthreads();
    }

    // h2 = relu(acc2 + rb2) -> smem chunks
#pragma unroll
    for (int mt = 0; mt < 2; mt++)
#pragma unroll
        for (int nt = 0; nt < 4; nt++) {
            int rowl = wm * 32 + mt * 16 + (lane >> 2);
            int col = wn * 32 + nt * 8 + (lane & 3) * 2;
            float b0 = rb2[col], b1 = rb2[col + 1];
            float v0 = fmaxf(acc2[mt][nt][0] + b0, 0.0f);
            float v1 = fmaxf(acc2[mt][nt][1] + b1, 0.0f);
            float v2 = fmaxf(acc2[mt][nt][2] + b0, 0.0f);
            float v3 = fmaxf(acc2[mt][nt][3] + b1, 0.0f);
            char* ckb = smem + H2OFF + (col >> 5) * H1CHK;
            int ci = (col & 31) * 2;
            __nv_bfloat16 h0, l0, h1, l1;
            split_bf16(v0, h0, l0); split_bf16(v1, h1, l1);
            *(uint32_t*)(ckb + rowl * PKB + ci)       = pck(h0, h1);
            *(uint32_t*)(ckb + APL + rowl * PKB + ci) = pck(l0, l1);
            split_bf16(v2, h0, l0); split_bf16(v3, h1, l1);
            *(uint32_t*)(ckb + (rowl + 8) * PKB + ci)       = pck(h0, h1);
            *(uint32_t*)(ckb + APL + (rowl + 8) * PKB + ci) = pck(l0, l1);
        }
    __syncthreads();

    // ================= PHASE 3: gemm3 128 -> 64 (all smem) ===================
    float acc3[2][2][4];
#pragma unroll
    for (int i = 0; i < 2; i++)
#pragma unroll
        for (int j = 0; j < 2; j++)
#pragma unroll
            for (int v = 0; v < 4; v++) acc3[i][j][v] = 0.0f;

    for (int c = 0; c < 4; c++) {
        char* abase = smem + H2OFF + c * H1CHK;
        char* bbase = smem + c * W3CHK;
#pragma unroll
        for (int kk = 0; kk < 2; kk++) {
            uint32_t afr[2][2][4];
#pragma unroll
            for (int pl = 0; pl < 2; pl++)
#pragma unroll
                for (int mt = 0; mt < 2; mt++) {
                    uint32_t a = smem_u32(abase + pl * APL
                        + (wm * 32 + mt * 16 + (lane & 15)) * PKB
                        + (kk * 16 + (lane >> 4) * 8) * 2);
                    ldm_x4(afr[pl][mt], a);
                }
#pragma unroll
            for (int nt = 0; nt < 2; nt++) {
                const char* bp = bbase
                    + (wn * 16 + nt * 8 + (lane >> 2)) * PKB
                    + (kk * 16 + (lane & 3) * 2) * 2;
                uint32_t bh[2], bl[2];
                bh[0] = *(const uint32_t*)bp;
                bh[1] = *(const uint32_t*)(bp + 16);
                bl[0] = *(const uint32_t*)(bp + 64 * PKB);
                bl[1] = *(const uint32_t*)(bp + 64 * PKB + 16);
#pragma unroll
                for (int mt = 0; mt < 2; mt++) {
                    mma16816(acc3[mt][nt], afr[0][mt], bh);
                    mma16816(acc3[mt][nt], afr[0][mt], bl);
                    mma16816(acc3[mt][nt], afr[1][mt], bh);
                }
            }
        }
    }
    __syncthreads();

    // ================= PHASE 4: relu(.+rb3) dot r4, reduce ==================
    float part[2][2] = {{0.0f, 0.0f}, {0.0f, 0.0f}};
#pragma unroll
    for (int mt = 0; mt < 2; mt++)
#pragma unroll
        for (int nt = 0; nt < 2; nt++) {
            int col = wn * 16 + nt * 8 + (lane & 3) * 2;
            float b0 = rb3[col], b1 = rb3[col + 1];
            float r0 = r4[col], r1 = r4[col + 1];
            part[mt][0] += fmaxf(acc3[mt][nt][0] + b0, 0.0f) * r0
                         + fmaxf(acc3[mt][nt][1] + b1, 0.0f) * r1;
            part[mt][1] += fmaxf(acc3[mt][nt][2] + b0, 0.0f) * r0
                         + fmaxf(acc3[mt][nt][3] + b1, 0.0f) * r1;
        }
    float* sp = (float*)(smem + SPOFF);   // [128][4]
#pragma unroll
    for (int mt = 0; mt < 2; mt++)
#pragma unroll
        for (int h = 0; h < 2; h++) {
            float v = part[mt][h];
            v += __shfl_xor_sync(0xffffffffu, v, 1);
            v += __shfl_xor_sync(0xffffffffu, v, 2);
            if ((lane & 3) == 0)
                sp[(wm * 32 + mt * 16 + h * 8 + (lane >> 2)) * 4 + wn] = v;
        }
    __syncthreads();
    if (t < 128)
        out[m0 + t] = sp[t * 4] + sp[t * 4 + 1] + sp[t * 4 + 2] + sp[t * 4 + 3] + rb4[0];
}

// ---------------- launch -----------------------------------------------------
extern "C" void kernel_launch(void* const* d_in, const int* in_sizes, int n_in,
                              void* d_out, int out_size) {
    const float* op  = (const float*)d_in[0];
    const float* qp  = (const float*)d_in[1];
    const float* w1  = (const float*)d_in[2];
    const float* b1  = (const float*)d_in[3];
    const float* w2  = (const float*)d_in[4];
    const float* b2  = (const float*)d_in[5];
    const float* w3  = (const float*)d_in[6];
    const float* b3  = (const float*)d_in[7];
    const float* r1  = (const float*)d_in[8];
    const float* rb1 = (const float*)d_in[9];
    const float* r2  = (const float*)d_in[10];
    const float* rb2 = (const float*)d_in[11];
    const float* r3  = (const float*)d_in[12];
    const float* rb3 = (const float*)d_in[13];
    const float* r4  = (const float*)d_in[14];
    const float* rb4 = (const float*)d_in[15];
    float* out = (float*)d_out;

    float* p_fall;
    cudaGetSymbolAddress((void**)&p_fall, g_fall);
    __nv_bfloat16 *r1h, *r1l, *r2h, *r2l, *r3h, *r3l;
    cudaGetSymbolAddress((void**)&r1h, g_r1h);  cudaGetSymbolAddress((void**)&r1l, g_r1l);
    cudaGetSymbolAddress((void**)&r2h, g_r2h);  cudaGetSymbolAddress((void**)&r2l, g_r2l);
    cudaGetSymbolAddress((void**)&r3h, g_r3h);  cudaGetSymbolAddress((void**)&r3l, g_r3l);

    cudaFuncSetAttribute(feature_mega, cudaFuncAttributeMaxDynamicSharedMemorySize, SMFEAT);
    cudaFuncSetAttribute(tgemm_mega,   cudaFuncAttributeMaxDynamicSharedMemorySize, SMEGA);

    // fork: knn + regressor weight split run concurrently with the feature chain
    cudaStream_t s2;
    cudaEvent_t e1, e2;
    cudaStreamCreateWithFlags(&s2, cudaStreamNonBlocking);
    cudaEventCreateWithFlags(&e1, cudaEventDisableTiming);
    cudaEventCreateWithFlags(&e2, cudaEventDisableTiming);
    cudaEventRecord(e1, 0);
    cudaStreamWaitEvent(s2, e1, 0);
    knn_part_kernel<<<dim3(NQ / 256, BATCH, 2), 256, 0, s2>>>(op, qp);
    knn_merge_kernel<<<NPTS / 256, 256, 0, s2>>>(op, qp);
    split_all_kernel<<<640, 256, 0, s2>>>(r1, r2, r3);
    cudaEventRecord(e2, s2);

    // main stream: feature chain (weights split inline) + bias fold
    feature_mega<<<NFCTA, 512, SMFEAT>>>(op, w1, b1, w2, b2, w3, b3);
    gbias_kernel<<<BATCH, 256>>>(r1, rb1);

    // join and run the regressor mega
    cudaStreamWaitEvent((cudaStream_t)0, e2, 0);
    tgemm_mega<<<NPTS / 128, 512, SMEGA>>>(
        p_fall, qp, r1h, r1l, r2h, r2l, r3h, r3l, rb2, rb3, r4, rb4, out);
}

// round 13
// speedup vs baseline: 1.0235x; 1.0235x over previous
#include <cuda_runtime.h>
#include <cuda_bf16.h>
#include <math_constants.h>
#include <cstdint>

#define BATCH 2
#define NP    4096
#define NPH   2048           // half of NP (knn split)
#define NQ    16384
#define FDIM  448            // 64 + 128 + 256
#define AGK   480            // gemm1 K: 448 interp + 3 query + 29 pad
#define NPTS  (BATCH * NQ)   // 32768 query points
#define MPTS  (BATCH * NP)   // 8192 original points

// ---------------- scratch (device globals; no allocation allowed) -----------
__device__ float g_fall[MPTS * FDIM];          // point-major fp32 (f1|f2|f3)
__device__ int   g_gmax[BATCH * 256];
__device__ float g_b1[BATCH * 256];            // gemm1 bias incl. global feats
__device__ int   g_knni[NPTS * 3];
__device__ float g_knnw[NPTS * 3];
__device__ float g_kcd[NPTS * 6];              // knn candidates (2 halves x 3)
__device__ int   g_kci[NPTS * 6];
__device__ __nv_bfloat16 g_w2h[128 * 64],   g_w2l[128 * 64];
__device__ __nv_bfloat16 g_w3h[256 * 128],  g_w3l[256 * 128];
__device__ __nv_bfloat16 g_r1h[256 * AGK],  g_r1l[256 * AGK];   // remapped cols
__device__ __nv_bfloat16 g_r2h[128 * 256],  g_r2l[128 * 256];
__device__ __nv_bfloat16 g_r3h[64 * 128],   g_r3l[64 * 128];

// ---------------- helpers -----------------------------------------------------
__device__ __forceinline__ uint32_t smem_u32(const void* p) {
    uint32_t a;
    asm("{ .reg .u64 t; cvta.to.shared.u64 t, %1; cvt.u32.u64 %0, t; }" : "=r"(a) : "l"(p));
    return a;
}
__device__ __forceinline__ void cp16(uint32_t dst, const void* src) {
    asm volatile("cp.async.cg.shared.global [%0], [%1], 16;" :: "r"(dst), "l"(src));
}
#define CP_COMMIT() asm volatile("cp.async.commit_group;" ::: "memory")

__device__ __forceinline__ void ldm_x4(uint32_t* r, uint32_t addr) {
    asm volatile("ldmatrix.sync.aligned.m8n8.x4.shared.b16 {%0,%1,%2,%3}, [%4];"
                 : "=r"(r[0]), "=r"(r[1]), "=r"(r[2]), "=r"(r[3]) : "r"(addr));
}
__device__ __forceinline__ void mma16816(float* c, const uint32_t* a, const uint32_t* b) {
    asm volatile(
        "mma.sync.aligned.m16n8k16.row.col.f32.bf16.bf16.f32 "
        "{%0,%1,%2,%3}, {%4,%5,%6,%7}, {%8,%9}, {%0,%1,%2,%3};"
        : "+f"(c[0]), "+f"(c[1]), "+f"(c[2]), "+f"(c[3])
        : "r"(a[0]), "r"(a[1]), "r"(a[2]), "r"(a[3]), "r"(b[0]), "r"(b[1]));
}
__device__ __forceinline__ void split_bf16(float v, __nv_bfloat16& h, __nv_bfloat16& l) {
    h = __float2bfloat16(v);
    l = __float2bfloat16(v - __bfloat162float(h));
}
__device__ __forceinline__ uint32_t pck(__nv_bfloat16 a, __nv_bfloat16 b) {
    return (uint32_t)*(unsigned short*)&a | ((uint32_t)*(unsigned short*)&b << 16);
}

#define PKB 80                       // smem row pitch bytes (32 bf16 + 16B pad)
#define APL (128 * PKB)              // A plane bytes (10240)
#define H1CHK (2 * APL)              // one staged chunk: hi+lo planes (20480)

// ---------------- gemm1 bias: rb1 + global-feature contribution (fp32) -------
__global__ void __launch_bounds__(256) gbias_kernel(const float* __restrict__ r1,
                                                    const float* __restrict__ rb1) {
    int b = blockIdx.x, n = threadIdx.x;
    const float* wr = r1 + n * 707 + 451;
    float acc = rb1[n];
#pragma unroll 8
    for (int j = 0; j < 256; j++)
        acc = fmaf(wr[j], __int_as_float(g_gmax[b * 256 + j]), acc);
    g_b1[b * 256 + n] = acc;
}

// ---------------- split_w: w2|w3 hi/lo split + g_gmax zero (main stream) -----
__global__ void __launch_bounds__(256) split_w_kernel(const float* __restrict__ w2,
                                                      const float* __restrict__ w3) {
    int i = blockIdx.x * 256 + threadIdx.x;
    if (i < BATCH * 256) g_gmax[i] = 0;   // relu outputs >= 0
    if (i >= 40960) return;
    float v;
    __nv_bfloat16 *hi, *lo; int off;
    if (i < 8192) { off = i;        hi = g_w2h; lo = g_w2l; v = w2[off]; }
    else          { off = i - 8192; hi = g_w3h; lo = g_w3l; v = w3[off]; }
    __nv_bfloat16 h, l; split_bf16(v, h, l);
    hi[off] = h; lo[off] = l;
}

// ---------------- split_r: r1 (remapped) | r2 | r3 (knn stream) --------------
__global__ void __launch_bounds__(256) split_r_kernel(
    const float* __restrict__ r1, const float* __restrict__ r2,
    const float* __restrict__ r3) {
    int i = blockIdx.x * 256 + threadIdx.x;
    if (i >= 163840) return;
    float v = 0.0f;
    __nv_bfloat16 *hi, *lo; int off;
    if (i < 122880) {
        off = i; hi = g_r1h; lo = g_r1l;
        int r = off / AGK, k = off - r * AGK;
        if (k < 448)      v = r1[r * 707 + 3 + k];     // interp channels
        else if (k < 451) v = r1[r * 707 + (k - 448)]; // query coords
    } else if (i < 155648) {
        off = i - 122880; hi = g_r2h; lo = g_r2l;
        v = r2[off];
    } else {
        off = i - 155648; hi = g_r3h; lo = g_r3l;
        v = r3[off];
    }
    __nv_bfloat16 h, l; split_bf16(v, h, l);
    hi[off] = h; lo[off] = l;
}

// ---------------- KNN part 1: top-3 within one half of the points ------------
__global__ void __launch_bounds__(256) knn_part_kernel(const float* __restrict__ op,
                                                       const float* __restrict__ qp) {
    __shared__ float4 sp[NPH];            // 32 KB
    int b = blockIdx.y, half = blockIdx.z;
    int tid = threadIdx.x;
    int jbase = half * NPH;
    for (int i = tid; i < NPH; i += 256) {
        float x = op[b * 3 * NP + 0 * NP + jbase + i];
        float y = op[b * 3 * NP + 1 * NP + jbase + i];
        float z = op[b * 3 * NP + 2 * NP + jbase + i];
        sp[i] = make_float4(x, y, z, fmaf(x, x, fmaf(y, y, z * z)));
    }
    __syncthreads();

    int q = blockIdx.x * 256 + tid;
    float qx = qp[b * 3 * NQ + 0 * NQ + q];
    float qy = qp[b * 3 * NQ + 1 * NQ + q];
    float qz = qp[b * 3 * NQ + 2 * NQ + q];
    float nx = -2.0f * qx, ny = -2.0f * qy, nz = -2.0f * qz;

    float d0 = CUDART_INF_F, d1 = CUDART_INF_F, d2 = CUDART_INF_F;
    int i0 = 0, i1 = 0, i2 = 0;
#pragma unroll 8
    for (int j = 0; j < NPH; j++) {
        float4 o = sp[j];
        float d = fmaf(o.x, nx, fmaf(o.y, ny, fmaf(o.z, nz, o.w)));
        if (d < d2) {
            if (d < d1) {
                d2 = d1; i2 = i1;
                if (d < d0) { d1 = d0; i1 = i0; d0 = d; i0 = j; }
                else        { d1 = d;  i1 = j; }
            } else { d2 = d; i2 = j; }
        }
    }
    int base = ((b * NQ + q) * 2 + half) * 3;
    g_kcd[base + 0] = d0; g_kci[base + 0] = jbase + i0;
    g_kcd[base + 1] = d1; g_kci[base + 1] = jbase + i1;
    g_kcd[base + 2] = d2; g_kci[base + 2] = jbase + i2;
}

// ---------------- KNN part 2: merge halves, compute weights ------------------
__global__ void __launch_bounds__(256) knn_merge_kernel(const float* __restrict__ op,
                                                        const float* __restrict__ qp) {
    int i = blockIdx.x * 256 + threadIdx.x;   // 0..NPTS-1
    int b = i >> 14, q = i & (NQ - 1);
    float d0 = CUDART_INF_F, d1 = CUDART_INF_F, d2 = CUDART_INF_F;
    int i0 = 0, i1 = 0, i2 = 0;
#pragma unroll
    for (int c = 0; c < 6; c++) {
        float d = g_kcd[i * 6 + c];
        int   j = g_kci[i * 6 + c];
        if (d < d2) {
            if (d < d1) {
                d2 = d1; i2 = i1;
                if (d < d0) { d1 = d0; i1 = i0; d0 = d; i0 = j; }
                else        { d1 = d;  i1 = j; }
            } else { d2 = d; i2 = j; }
        }
    }
    float qx = qp[b * 3 * NQ + 0 * NQ + q];
    float qy = qp[b * 3 * NQ + 1 * NQ + q];
    float qz = qp[b * 3 * NQ + 2 * NQ + q];
    int   ii[3] = {i0, i1, i2};
    float rc[3];
    float s = 0.0f;
#pragma unroll
    for (int k = 0; k < 3; k++) {
        float dx = op[b * 3 * NP + 0 * NP + ii[k]] - qx;
        float dy = op[b * 3 * NP + 1 * NP + ii[k]] - qy;
        float dz = op[b * 3 * NP + 2 * NP + ii[k]] - qz;
        float dist = sqrtf(fmaf(dx, dx, fmaf(dy, dy, dz * dz)));
        rc[k] = 1.0f / (dist + 1e-8f);
        s += rc[k];
    }
    float inv = 1.0f / s;
#pragma unroll
    for (int k = 0; k < 3; k++) {
        g_knni[i * 3 + k] = ii[k];
        g_knnw[i * 3 + k] = rc[k] * inv;
    }
}

// ---------------- FEATURE MEGA: mlp1 -> mlp2 -> mlp3 -> gmax, one kernel -----
//   [0,      40960)  f1 chunks (2 x 20480)
//   [40960, 122880)  f2 chunks (4 x 20480)
//   [122880,163840)  W buffer (W2: 2x10240 | W3: 2x20480)
//   [163840,164864)  w1 (192) + b1 (64) floats
#define FH1  0
#define FH2  40960
#define FWO  122880
#define FCO  163840
#define SMFEAT 164864

__global__ void __launch_bounds__(512) feature_mega(
    const float* __restrict__ op,
    const float* __restrict__ w1, const float* __restrict__ b1,
    const __nv_bfloat16* __restrict__ W2hi, const __nv_bfloat16* __restrict__ W2lo,
    const float* __restrict__ b2,
    const __nv_bfloat16* __restrict__ W3hi, const __nv_bfloat16* __restrict__ W3lo,
    const float* __restrict__ b3) {
    extern __shared__ char smem[];
    const int t = threadIdx.x;
    const int lane = t & 31, warp = t >> 5;
    const int wm = warp >> 2, wn = warp & 3;
    const int m0 = blockIdx.x * 128;
    const int b  = m0 >> 12;
    const int pt0 = m0 & (NP - 1);

    float* sw1 = (float*)(smem + FCO);
    float* sb1 = sw1 + 192;
    if (t < 192) sw1[t] = w1[t];
    else if (t < 256) sb1[t - 192] = b1[t - 192];
    __syncthreads();

    // ---- phase A: f1 = relu(w1*xyz + b1), fp32 to fall + smem chunks --------
#pragma unroll
    for (int u = 0; u < 2; u++) {
        int e = t + u * 512;
        int row = e >> 3, c8 = e & 7;
        int pt = pt0 + row;
        float x = op[b * 3 * NP + pt];
        float y = op[b * 3 * NP + NP + pt];
        float z = op[b * 3 * NP + 2 * NP + pt];
        float v[8];
        __nv_bfloat16 h[8], l[8];
#pragma unroll
        for (int j = 0; j < 8; j++) {
            int c = c8 * 8 + j;
            v[j] = fmaxf(fmaf(sw1[c*3], x, fmaf(sw1[c*3+1], y,
                        fmaf(sw1[c*3+2], z, sb1[c]))), 0.0f);
            split_bf16(v[j], h[j], l[j]);
        }
        float* fd = g_fall + (size_t)(m0 + row) * FDIM + c8 * 8;
        *(float4*)fd       = make_float4(v[0], v[1], v[2], v[3]);
        *(float4*)(fd + 4) = make_float4(v[4], v[5], v[6], v[7]);
        char* ckb = smem + FH1 + (c8 >> 2) * H1CHK;
        int off = row * PKB + (c8 & 3) * 16;
        *(uint4*)(ckb + off) =
            make_uint4(pck(h[0],h[1]), pck(h[2],h[3]), pck(h[4],h[5]), pck(h[6],h[7]));
        *(uint4*)(ckb + APL + off) =
            make_uint4(pck(l[0],l[1]), pck(l[2],l[3]), pck(l[4],l[5]), pck(l[6],l[7]));
    }
    __syncthreads();

    // ---- phase B: gemm 64 -> 128 (W2 streamed per chunk) --------------------
    constexpr int W2PL = 128 * PKB;   // 10240
    float acc2[2][4][4];
#pragma unroll
    for (int i = 0; i < 2; i++)
#pragma unroll
        for (int j = 0; j < 4; j++)
#pragma unroll
            for (int v = 0; v < 4; v++) acc2[i][j][v] = 0.0f;

    for (int c = 0; c < 2; c++) {
#pragma unroll
        for (int u = 0; u < 2; u++) {
            int e = t + u * 512;
            int pl = e >> 9, rem = e & 511;
            int row = rem >> 2, seg = rem & 3;
            const char* src = (const char*)(pl ? W2lo : W2hi)
                + ((size_t)row * 64 + c * 32) * 2 + seg * 16;
            cp16(smem_u32(smem + FWO + pl * W2PL + row * PKB + seg * 16), src);
        }
        CP_COMMIT();
        asm volatile("cp.async.wait_group 0;" ::: "memory");
        __syncthreads();

        char* abase = smem + FH1 + c * H1CHK;
#pragma unroll
        for (int kk = 0; kk < 2; kk++) {
            uint32_t afr[2][2][4];
#pragma unroll
            for (int pl = 0; pl < 2; pl++)
#pragma unroll
                for (int mt = 0; mt < 2; mt++) {
                    uint32_t a = smem_u32(abase + pl * APL
                        + (wm * 32 + mt * 16 + (lane & 15)) * PKB
                        + (kk * 16 + (lane >> 4) * 8) * 2);
                    ldm_x4(afr[pl][mt], a);
                }
#pragma unroll
            for (int nt = 0; nt < 4; nt++) {
                const char* bp = smem + FWO
                    + (wn * 32 + nt * 8 + (lane >> 2)) * PKB
                    + (kk * 16 + (lane & 3) * 2) * 2;
                uint32_t bh[2], bl[2];
                bh[0] = *(const uint32_t*)bp;
                bh[1] = *(const uint32_t*)(bp + 16);
                bl[0] = *(const uint32_t*)(bp + W2PL);
                bl[1] = *(const uint32_t*)(bp + W2PL + 16);
#pragma unroll
                for (int mt = 0; mt < 2; mt++) {
                    mma16816(acc2[mt][nt], afr[0][mt], bh);
                    mma16816(acc2[mt][nt], afr[0][mt], bl);
                    mma16816(acc2[mt][nt], afr[1][mt], bh);
                }
            }
        }
        __syncthreads();
    }

    // f2 = relu(acc2 + b2): fp32 to fall col 64.. + smem chunks
#pragma unroll
    for (int mt = 0; mt < 2; mt++)
#pragma unroll
        for (int nt = 0; nt < 4; nt++) {
            int rowl = wm * 32 + mt * 16 + (lane >> 2);
            int col = wn * 32 + nt * 8 + (lane & 3) * 2;
            float b0 = b2[col], b1v = b2[col + 1];
            float v0 = fmaxf(acc2[mt][nt][0] + b0, 0.0f);
            float v1 = fmaxf(acc2[mt][nt][1] + b1v, 0.0f);
            float v2 = fmaxf(acc2[mt][nt][2] + b0, 0.0f);
            float v3 = fmaxf(acc2[mt][nt][3] + b1v, 0.0f);
            *(float2*)(g_fall + (size_t)(m0 + rowl) * FDIM + 64 + col) = make_float2(v0, v1);
            *(float2*)(g_fall + (size_t)(m0 + rowl + 8) * FDIM + 64 + col) = make_float2(v2, v3);
            char* ckb = smem + FH2 + (col >> 5) * H1CHK;
            int ci = (col & 31) * 2;
            __nv_bfloat16 h0, l0, h1, l1;
            split_bf16(v0, h0, l0); split_bf16(v1, h1, l1);
            *(uint32_t*)(ckb + rowl * PKB + ci)       = pck(h0, h1);
            *(uint32_t*)(ckb + APL + rowl * PKB + ci) = pck(l0, l1);
            split_bf16(v2, h0, l0); split_bf16(v3, h1, l1);
            *(uint32_t*)(ckb + (rowl + 8) * PKB + ci)       = pck(h0, h1);
            *(uint32_t*)(ckb + APL + (rowl + 8) * PKB + ci) = pck(l0, l1);
        }
    __syncthreads();

    // ---- phase C: gemm 128 -> 256 (W3 streamed per chunk) -------------------
    constexpr int W3PL = 256 * PKB;   // 20480
    float acc3[2][8][4];
#pragma unroll
    for (int i = 0; i < 2; i++)
#pragma unroll
        for (int j = 0; j < 8; j++)
#pragma unroll
            for (int v = 0; v < 4; v++) acc3[i][j][v] = 0.0f;

    for (int c = 0; c < 4; c++) {
#pragma unroll
        for (int u = 0; u < 4; u++) {
            int e = t + u * 512;
            int pl = e >> 10, rem = e & 1023;
            int row = rem >> 2, seg = rem & 3;
            const char* src = (const char*)(pl ? W3lo : W3hi)
                + ((size_t)row * 128 + c * 32) * 2 + seg * 16;
            cp16(smem_u32(smem + FWO + pl * W3PL + row * PKB + seg * 16), src);
        }
        CP_COMMIT();
        asm volatile("cp.async.wait_group 0;" ::: "memory");
        __syncthreads();

        char* abase = smem + FH2 + c * H1CHK;
#pragma unroll
        for (int kk = 0; kk < 2; kk++) {
            uint32_t afr[2][2][4];
#pragma unroll
            for (int pl = 0; pl < 2; pl++)
#pragma unroll
                for (int mt = 0; mt < 2; mt++) {
                    uint32_t a = smem_u32(abase + pl * APL
                        + (wm * 32 + mt * 16 + (lane & 15)) * PKB
                        + (kk * 16 + (lane >> 4) * 8) * 2);
                    ldm_x4(afr[pl][mt], a);
                }
#pragma unroll
            for (int nt = 0; nt < 8; nt++) {
                const char* bp = smem + FWO
                    + (wn * 64 + nt * 8 + (lane >> 2)) * PKB
                    + (kk * 16 + (lane & 3) * 2) * 2;
                uint32_t bh[2], bl[2];
                bh[0] = *(const uint32_t*)bp;
                bh[1] = *(const uint32_t*)(bp + 16);
                bl[0] = *(const uint32_t*)(bp + W3PL);
                bl[1] = *(const uint32_t*)(bp + W3PL + 16);
#pragma unroll
                for (int mt = 0; mt < 2; mt++) {
                    mma16816(acc3[mt][nt], afr[0][mt], bh);
                    mma16816(acc3[mt][nt], afr[0][mt], bl);
                    mma16816(acc3[mt][nt], afr[1][mt], bh);
                }
            }
        }
        __syncthreads();
    }

    // f3 = relu(acc3 + b3): fp32 to fall col 192.. + fused gmax
#pragma unroll
    for (int mt = 0; mt < 2; mt++)
#pragma unroll
        for (int nt = 0; nt < 8; nt++) {
            int rowl = wm * 32 + mt * 16 + (lane >> 2);
            int col = wn * 64 + nt * 8 + (lane & 3) * 2;
            float b0 = b3[col], b1v = b3[col + 1];
            float v0 = fmaxf(acc3[mt][nt][0] + b0, 0.0f);
            float v1 = fmaxf(acc3[mt][nt][1] + b1v, 0.0f);
            float v2 = fmaxf(acc3[mt][nt][2] + b0, 0.0f);
            float v3 = fmaxf(acc3[mt][nt][3] + b1v, 0.0f);
            *(float2*)(g_fall + (size_t)(m0 + rowl) * FDIM + 192 + col) = make_float2(v0, v1);
            *(float2*)(g_fall + (size_t)(m0 + rowl + 8) * FDIM + 192 + col) = make_float2(v2, v3);
        }
#pragma unroll
    for (int nt = 0; nt < 8; nt++) {
        int col = wn * 64 + nt * 8 + (lane & 3) * 2;
        float b0 = b3[col], b1v = b3[col + 1];
        float mA = fmaxf(fmaxf(acc3[0][nt][0], acc3[0][nt][2]),
                         fmaxf(acc3[1][nt][0], acc3[1][nt][2])) + b0;
        float mB = fmaxf(fmaxf(acc3[0][nt][1], acc3[0][nt][3]),
                         fmaxf(acc3[1][nt][1], acc3[1][nt][3])) + b1v;
        mA = fmaxf(mA, 0.0f); mB = fmaxf(mB, 0.0f);
#pragma unroll
        for (int o = 4; o < 32; o <<= 1) {
            mA = fmaxf(mA, __shfl_xor_sync(0xffffffffu, mA, o));
            mB = fmaxf(mB, __shfl_xor_sync(0xffffffffu, mB, o));
        }
        if ((lane >> 2) == 0) {
            atomicMax(&g_gmax[b * 256 + col],     __float_as_int(mA));
            atomicMax(&g_gmax[b * 256 + col + 1], __float_as_int(mB));
        }
    }
}

// ---------------- MEGA: gemm1(interp,480->256) -> 256->128 -> 128->64 -> 1 ---
#define SS1    (2 * APL + 2 * 256 * PKB)   // 61440
#define W3CHK  (2 * 64 * PKB)              // 10240
#define G1OFF  40960
#define KOFF   163840
#define H1OFF  40960
#define W2OFF  204800
#define W2PLM  (128 * PKB)                 // 10240
#define H2OFF  40960
#define SPOFF  163840
#define SMEGA  225280

__global__ void __launch_bounds__(512) tgemm_mega(
    const float* __restrict__ fall, const float* __restrict__ qp,
    const __nv_bfloat16* __restrict__ W1hi, const __nv_bfloat16* __restrict__ W1lo,
    const __nv_bfloat16* __restrict__ W2hi, const __nv_bfloat16* __restrict__ W2lo,
    const __nv_bfloat16* __restrict__ W3hi, const __nv_bfloat16* __restrict__ W3lo,
    const float* __restrict__ rb2, const float* __restrict__ rb3,
    const float* __restrict__ r4, const float* __restrict__ rb4,
    float* __restrict__ out) {
    extern __shared__ char smem[];
    const int t = threadIdx.x;
    const int lane = t & 31, warp = t >> 5;
    const int wm = warp >> 2, wn = warp & 3;
    const int m0 = blockIdx.x * 128;
    const int b  = m0 >> 14;

    int*   si  = (int*)(smem + KOFF);
    float* swt = (float*)(smem + KOFF + 1536);
    if (t < 128) {
#pragma unroll
        for (int j = 0; j < 3; j++) {
            si[t * 3 + j]  = g_knni[(m0 + t) * 3 + j];
            swt[t * 3 + j] = g_knnw[(m0 + t) * 3 + j];
        }
    }

    // r3 preload into [0, 40960): joins the first cp.async group
    {
        char* w3b = smem;
#pragma unroll
        for (int u = 0; u < 4; u++) {
            int e = t + u * 512;
            int pl = e >> 10, rem = e & 1023;
            int ck = rem >> 8, r2m = rem & 255;
            int row = r2m >> 2, seg = r2m & 3;
            const char* src = (const char*)(pl ? W3lo : W3hi)
                + ((size_t)row * 128 + ck * 32) * 2 + seg * 16;
            cp16(smem_u32(w3b + ck * W3CHK + pl * (64 * PKB) + row * PKB + seg * 16), src);
        }
    }

    // ================= PHASE 1: gemm1 480 -> 256 =================
    constexpr int NC1 = AGK / 32;   // 15
    float acc[2][8][4];
#pragma unroll
    for (int i = 0; i < 2; i++)
#pragma unroll
        for (int j = 0; j < 8; j++)
#pragma unroll
            for (int v = 0; v < 4; v++) acc[i][j][v] = 0.0f;

    auto stageW1 = [&](int buf, int c) {
        char* base = smem + G1OFF + buf * SS1;
#pragma unroll
        for (int u = 0; u < 4; u++) {
            int e = t + u * 512;
            int pl = e >> 10, rem = e & 1023;
            int row = rem >> 2, seg = rem & 3;
            const char* src = (const char*)(pl ? W1lo : W1hi)
                + ((size_t)row * AGK + c * 32) * 2 + seg * 16;
            cp16(smem_u32(base + 2 * APL + pl * (256 * PKB) + row * PKB + seg * 16), src);
        }
        CP_COMMIT();
    };

    auto stageA1 = [&](char* base, int c) {
        const int ch0 = c * 32;
#pragma unroll
        for (int u = 0; u < 2; u++) {
            int e = t + u * 512;
            int row = e >> 3, c4 = e & 7;
            int ch = ch0 + c4 * 4;
            float v0, v1, v2, v3;
            if (ch < 448) {
                const float* fr = fall + (size_t)(b * NP) * FDIM + ch;
                float4 A = *(const float4*)(fr + (size_t)si[row * 3 + 0] * FDIM);
                float4 B = *(const float4*)(fr + (size_t)si[row * 3 + 1] * FDIM);
                float4 C = *(const float4*)(fr + (size_t)si[row * 3 + 2] * FDIM);
                float wa = swt[row * 3 + 0], wb = swt[row * 3 + 1], wc = swt[row * 3 + 2];
                v0 = wa * A.x + wb * B.x + wc * C.x;
                v1 = wa * A.y + wb * B.y + wc * C.y;
                v2 = wa * A.z + wb * B.z + wc * C.z;
                v3 = wa * A.w + wb * B.w + wc * C.w;
            } else if (ch == 448) {
                int qi = (m0 + row) & (NQ - 1);
                v0 = qp[b * 3 * NQ + 0 * NQ + qi];
                v1 = qp[b * 3 * NQ + 1 * NQ + qi];
                v2 = qp[b * 3 * NQ + 2 * NQ + qi];
                v3 = 0.0f;
            } else {
                v0 = v1 = v2 = v3 = 0.0f;
            }
            __nv_bfloat16 h0, l0, h1, l1, h2, l2, h3, l3;
            split_bf16(v0, h0, l0); split_bf16(v1, h1, l1);
            split_bf16(v2, h2, l2); split_bf16(v3, h3, l3);
            int off = row * PKB + (c4 >> 1) * 16 + (c4 & 1) * 8;
            *(uint2*)(base + off)       = make_uint2(pck(h0, h1), pck(h2, h3));
            *(uint2*)(base + APL + off) = make_uint2(pck(l0, l1), pck(l2, l3));
        }
    };

    __syncthreads();   // si/swt visible before stageA uses them
    stageW1(0, 0);
    for (int c = 0; c < NC1; c++) {
        char* base = smem + G1OFF + (c & 1) * SS1;
        stageA1(base, c);
        if (c + 1 < NC1) {
            stageW1((c + 1) & 1, c + 1);
            asm volatile("cp.async.wait_group 1;" ::: "memory");
        } else {
            asm volatile("cp.async.wait_group 0;" ::: "memory");
        }
        __syncthreads();
#pragma unroll
        for (int kk = 0; kk < 2; kk++) {
            uint32_t afr[2][2][4];
#pragma unroll
            for (int pl = 0; pl < 2; pl++)
#pragma unroll
                for (int mt = 0; mt < 2; mt++) {
                    uint32_t a = smem_u32(base + pl * APL
                        + (wm * 32 + mt * 16 + (lane & 15)) * PKB
                        + (kk * 16 + (lane >> 4) * 8) * 2);
                    ldm_x4(afr[pl][mt], a);
                }
#pragma unroll
            for (int nt = 0; nt < 8; nt++) {
                const char* bp = base + 2 * APL
                    + (wn * 64 + nt * 8 + (lane >> 2)) * PKB
                    + (kk * 16 + (lane & 3) * 2) * 2;
                uint32_t bh[2], bl[2];
                bh[0] = *(const uint32_t*)bp;
                bh[1] = *(const uint32_t*)(bp + 16);
                bl[0] = *(const uint32_t*)(bp + 256 * PKB);
                bl[1] = *(const uint32_t*)(bp + 256 * PKB + 16);
#pragma unroll
                for (int mt = 0; mt < 2; mt++) {
                    mma16816(acc[mt][nt], afr[0][mt], bh);
                    mma16816(acc[mt][nt], afr[0][mt], bl);
                    mma16816(acc[mt][nt], afr[1][mt], bh);
                }
            }
        }
        __syncthreads();
    }

    // h1 = relu(acc + g_b1) -> smem chunk layout
    {
        const float* bias = g_b1 + b * 256;
#pragma unroll
        for (int mt = 0; mt < 2; mt++)
#pragma unroll
            for (int nt = 0; nt < 8; nt++) {
                int rowl = wm * 32 + mt * 16 + (lane >> 2);
                int col = wn * 64 + nt * 8 + (lane & 3) * 2;
                float b0 = bias[col], b1 = bias[col + 1];
                float v0 = fmaxf(acc[mt][nt][0] + b0, 0.0f);
                float v1 = fmaxf(acc[mt][nt][1] + b1, 0.0f);
                float v2 = fmaxf(acc[mt][nt][2] + b0, 0.0f);
                float v3 = fmaxf(acc[mt][nt][3] + b1, 0.0f);
                char* ckb = smem + H1OFF + (col >> 5) * H1CHK;
                int ci = (col & 31) * 2;
                __nv_bfloat16 h0, l0, h1, l1;
                split_bf16(v0, h0, l0); split_bf16(v1, h1, l1);
                *(uint32_t*)(ckb + rowl * PKB + ci)       = pck(h0, h1);
                *(uint32_t*)(ckb + APL + rowl * PKB + ci) = pck(l0, l1);
                split_bf16(v2, h0, l0); split_bf16(v3, h1, l1);
                *(uint32_t*)(ckb + (rowl + 8) * PKB + ci)       = pck(h0, h1);
                *(uint32_t*)(ckb + APL + (rowl + 8) * PKB + ci) = pck(l0, l1);
            }
    }
    __syncthreads();

    // ================= PHASE 2: gemm2 256 -> 128 (W2 single buffer) ==========
    float acc2[2][4][4];
#pragma unroll
    for (int i = 0; i < 2; i++)
#pragma unroll
        for (int j = 0; j < 4; j++)
#pragma unroll
            for (int v = 0; v < 4; v++) acc2[i][j][v] = 0.0f;

    for (int c = 0; c < 8; c++) {
#pragma unroll
        for (int u = 0; u < 2; u++) {
            int e = t + u * 512;
            int pl = e >> 9, rem = e & 511;
            int row = rem >> 2, seg = rem & 3;
            const char* src = (const char*)(pl ? W2lo : W2hi)
                + ((size_t)row * 256 + c * 32) * 2 + seg * 16;
            cp16(smem_u32(smem + W2OFF + pl * W2PLM + row * PKB + seg * 16), src);
        }
        CP_COMMIT();
        asm volatile("cp.async.wait_group 0;" ::: "memory");
        __syncthreads();

        char* abase = smem + H1OFF + c * H1CHK;
#pragma unroll
        for (int kk = 0; kk < 2; kk++) {
            uint32_t afr[2][2][4];
#pragma unroll
            for (int pl = 0; pl < 2; pl++)
#pragma unroll
                for (int mt = 0; mt < 2; mt++) {
                    uint32_t a = smem_u32(abase + pl * APL
                        + (wm * 32 + mt * 16 + (lane & 15)) * PKB
                        + (kk * 16 + (lane >> 4) * 8) * 2);
                    ldm_x4(afr[pl][mt], a);
                }
#pragma unroll
            for (int nt = 0; nt < 4; nt++) {
                const char* bp = smem + W2OFF
                    + (wn * 32 + nt * 8 + (lane >> 2)) * PKB
                    + (kk * 16 + (lane & 3) * 2) * 2;
                uint32_t bh[2], bl[2];
                bh[0] = *(const uint32_t*)bp;
                bh[1] = *(const uint32_t*)(bp + 16);
                bl[0] = *(const uint32_t*)(bp + W2PLM);
                bl[1] = *(const uint32_t*)(bp + W2PLM + 16);
#pragma unroll
                for (int mt = 0; mt < 2; mt++) {
                    mma16816(acc2[mt][nt], afr[0][mt], bh);
                    mma16816(acc2[mt][nt], afr[0][mt], bl);
                    mma16816(acc2[mt][nt], afr[1][mt], bh);
                }
            }
        }
        __syncthreads();
    }

    // h2 = relu(acc2 + rb2) -> smem chunks
#pragma unroll
    for (int mt = 0; mt < 2; mt++)
#pragma unroll
        for (int nt = 0; nt < 4; nt++) {
            int rowl = wm * 32 + mt * 16 + (lane >> 2);
            int col = wn * 32 + nt * 8 + (lane & 3) * 2;
            float b0 = rb2[col], b1 = rb2[col + 1];
            float v0 = fmaxf(acc2[mt][nt][0] + b0, 0.0f);
            float v1 = fmaxf(acc2[mt][nt][1] + b1, 0.0f);
            float v2 = fmaxf(acc2[mt][nt][2] + b0, 0.0f);
            float v3 = fmaxf(acc2[mt][nt][3] + b1, 0.0f);
            char* ckb = smem + H2OFF + (col >> 5) * H1CHK;
            int ci = (col & 31) * 2;
            __nv_bfloat16 h0, l0, h1, l1;
            split_bf16(v0, h0, l0); split_bf16(v1, h1, l1);
            *(uint32_t*)(ckb + rowl * PKB + ci)       = pck(h0, h1);
            *(uint32_t*)(ckb + APL + rowl * PKB + ci) = pck(l0, l1);
            split_bf16(v2, h0, l0); split_bf16(v3, h1, l1);
            *(uint32_t*)(ckb + (rowl + 8) * PKB + ci)       = pck(h0, h1);
            *(uint32_t*)(ckb + APL + (rowl + 8) * PKB + ci) = pck(l0, l1);
        }
    __syncthreads();

    // ================= PHASE 3: gemm3 128 -> 64 (all smem) ===================
    float acc3[2][2][4];
#pragma unroll
    for (int i = 0; i < 2; i++)
#pragma unroll
        for (int j = 0; j < 2; j++)
#pragma unroll
            for (int v = 0; v < 4; v++) acc3[i][j][v] = 0.0f;

    for (int c = 0; c < 4; c++) {
        char* abase = smem + H2OFF + c * H1CHK;
        char* bbase = smem + c * W3CHK;
#pragma unroll
        for (int kk = 0; kk < 2; kk++) {
            uint32_t afr[2][2][4];
#pragma unroll
            for (int pl = 0; pl < 2; pl++)
#pragma unroll
                for (int mt = 0; mt < 2; mt++) {
                    uint32_t a = smem_u32(abase + pl * APL
                        + (wm * 32 + mt * 16 + (lane & 15)) * PKB
                        + (kk * 16 + (lane >> 4) * 8) * 2);
                    ldm_x4(afr[pl][mt], a);
                }
#pragma unroll
            for (int nt = 0; nt < 2; nt++) {
                const char* bp = bbase
                    + (wn * 16 + nt * 8 + (lane >> 2)) * PKB
                    + (kk * 16 + (lane & 3) * 2) * 2;
                uint32_t bh[2], bl[2];
                bh[0] = *(const uint32_t*)bp;
                bh[1] = *(const uint32_t*)(bp + 16);
                bl[0] = *(const uint32_t*)(bp + 64 * PKB);
                bl[1] = *(const uint32_t*)(bp + 64 * PKB + 16);
#pragma unroll
                for (int mt = 0; mt < 2; mt++) {
                    mma16816(acc3[mt][nt], afr[0][mt], bh);
                    mma16816(acc3[mt][nt], afr[0][mt], bl);
                    mma16816(acc3[mt][nt], afr[1][mt], bh);
                }
            }
        }
    }
    __syncthreads();

    // ================= PHASE 4: relu(.+rb3) dot r4, reduce ==================
    float part[2][2] = {{0.0f, 0.0f}, {0.0f, 0.0f}};
#pragma unroll
    for (int mt = 0; mt < 2; mt++)
#pragma unroll
        for (int nt = 0; nt < 2; nt++) {
            int col = wn * 16 + nt * 8 + (lane & 3) * 2;
            float b0 = rb3[col], b1 = rb3[col + 1];
            float r0 = r4[col], r1 = r4[col + 1];
            part[mt][0] += fmaxf(acc3[mt][nt][0] + b0, 0.0f) * r0
                         + fmaxf(acc3[mt][nt][1] + b1, 0.0f) * r1;
            part[mt][1] += fmaxf(acc3[mt][nt][2] + b0, 0.0f) * r0
                         + fmaxf(acc3[mt][nt][3] + b1, 0.0f) * r1;
        }
    float* sp = (float*)(smem + SPOFF);   // [128][4]
#pragma unroll
    for (int mt = 0; mt < 2; mt++)
#pragma unroll
        for (int h = 0; h < 2; h++) {
            float v = part[mt][h];
            v += __shfl_xor_sync(0xffffffffu, v, 1);
            v += __shfl_xor_sync(0xffffffffu, v, 2);
            if ((lane & 3) == 0)
                sp[(wm * 32 + mt * 16 + h * 8 + (lane >> 2)) * 4 + wn] = v;
        }
    __syncthreads();
    if (t < 128)
        out[m0 + t] = sp[t * 4] + sp[t * 4 + 1] + sp[t * 4 + 2] + sp[t * 4 + 3] + rb4[0];
}

// ---------------- launch -----------------------------------------------------
extern "C" void kernel_launch(void* const* d_in, const int* in_sizes, int n_in,
                              void* d_out, int out_size) {
    const float* op  = (const float*)d_in[0];
    const float* qp  = (const float*)d_in[1];
    const float* w1  = (const float*)d_in[2];
    const float* b1  = (const float*)d_in[3];
    const float* w2  = (const float*)d_in[4];
    const float* b2  = (const float*)d_in[5];
    const float* w3  = (const float*)d_in[6];
    const float* b3  = (const float*)d_in[7];
    const float* r1  = (const float*)d_in[8];
    const float* rb1 = (const float*)d_in[9];
    const float* r2  = (const float*)d_in[10];
    const float* rb2 = (const float*)d_in[11];
    const float* r3  = (const float*)d_in[12];
    const float* rb3 = (const float*)d_in[13];
    const float* r4  = (const float*)d_in[14];
    const float* rb4 = (const float*)d_in[15];
    float* out = (float*)d_out;

    float* p_fall;
    cudaGetSymbolAddress((void**)&p_fall, g_fall);
    __nv_bfloat16 *w2h, *w2l, *w3h, *w3l, *r1h, *r1l, *r2h, *r2l, *r3h, *r3l;
    cudaGetSymbolAddress((void**)&w2h, g_w2h);  cudaGetSymbolAddress((void**)&w2l, g_w2l);
    cudaGetSymbolAddress((void**)&w3h, g_w3h);  cudaGetSymbolAddress((void**)&w3l, g_w3l);
    cudaGetSymbolAddress((void**)&r1h, g_r1h);  cudaGetSymbolAddress((void**)&r1l, g_r1l);
    cudaGetSymbolAddress((void**)&r2h, g_r2h);  cudaGetSymbolAddress((void**)&r2l, g_r2l);
    cudaGetSymbolAddress((void**)&r3h, g_r3h);  cudaGetSymbolAddress((void**)&r3l, g_r3l);

    cudaFuncSetAttribute(feature_mega, cudaFuncAttributeMaxDynamicSharedMemorySize, SMFEAT);
    cudaFuncSetAttribute(tgemm_mega,   cudaFuncAttributeMaxDynamicSharedMemorySize, SMEGA);

    // fork: knn + regressor weight split run concurrently with the feature chain
    cudaStream_t s2;
    cudaEvent_t e1, e2;
    cudaStreamCreateWithFlags(&s2, cudaStreamNonBlocking);
    cudaEventCreateWithFlags(&e1, cudaEventDisableTiming);
    cudaEventCreateWithFlags(&e2, cudaEventDisableTiming);
    cudaEventRecord(e1, 0);
    cudaStreamWaitEvent(s2, e1, 0);
    knn_part_kernel<<<dim3(NQ / 256, BATCH, 2), 256, 0, s2>>>(op, qp);
    knn_merge_kernel<<<NPTS / 256, 256, 0, s2>>>(op, qp);
    split_r_kernel<<<640, 256, 0, s2>>>(r1, r2, r3);
    cudaEventRecord(e2, s2);

    // main stream: w-split (+gmax zero) -> feature chain -> bias fold
    split_w_kernel<<<160, 256>>>(w2, w3);
    feature_mega<<<MPTS / 128, 512, SMFEAT>>>(op, w1, b1, w2h, w2l, b2, w3h, w3l, b3);
    gbias_kernel<<<BATCH, 256>>>(r1, rb1);

    // join and run the regressor mega
    cudaStreamWaitEvent((cudaStream_t)0, e2, 0);
    tgemm_mega<<<NPTS / 128, 512, SMEGA>>>(
        p_fall, qp, r1h, r1l, r2h, r2l, r3h, r3l, rb2, rb3, r4, rb4, out);
}